// round 1
// baseline (speedup 1.0000x reference)
#include <cuda_runtime.h>
#include <math.h>

#define NB 8
#define NTOK 4096
#define NC 256
#define NHEAD 8
#define HD 32
#define RDIM 64
#define TILE 16

// Scratch (device globals: no allocation allowed)
__device__ float g_kv[NB * NHEAD * HD * HD];   // 65536 floats
__device__ float g_ksum[NB * NHEAD * HD];      // 2048 floats
__device__ float g_alpha[NB * NTOK];           // 32768 floats

// ---------------------------------------------------------------------------
// Kernel 0: zero the accumulators (must run every launch; graph replays reuse
// the globals).
// ---------------------------------------------------------------------------
__global__ void k_zero() {
    int i = blockIdx.x * blockDim.x + threadIdx.x;
    if (i < NB * NHEAD * HD * HD) g_kv[i] = 0.f;
    if (i < NB * NHEAD * HD)      g_ksum[i] = 0.f;
}

// ---------------------------------------------------------------------------
// Kernel 1: per-token focused k' computation + kv / ksum accumulation + alpha_q.
// One warp per token; 8 warps/block stage k' and v rows in smem, then the
// block does an outer-product accumulation with thread (h,d) owning kv[h][d][*].
// ---------------------------------------------------------------------------
__global__ __launch_bounds__(256) void k_stats(
    const float* __restrict__ qkv,
    const float* __restrict__ pos,
    const float* __restrict__ scale)
{
    __shared__ float s_isc[NC];
    __shared__ float sk[8][NC];
    __shared__ float sv[8][NC];

    const int tid  = threadIdx.x;
    const int wid  = tid >> 5;
    const int lane = tid & 31;
    const int b    = blockIdx.y;

    if (tid < NC) s_isc[tid] = 1.f / log1pf(expf(scale[tid]));
    __syncthreads();

    const float* qb = qkv + (size_t)b * NTOK * NC;
    const float* kb = qkv + ((size_t)NB + b) * NTOK * NC;
    const float* vb = qkv + ((size_t)2 * NB + b) * NTOK * NC;

    // Accumulation ownership: h = tid>>5 (== wid), d = lane
    const int h = wid;
    const int d = lane;
    float acc[HD];
#pragma unroll
    for (int e = 0; e < HD; ++e) acc[e] = 0.f;
    float accs = 0.f;

    const int chunk = NTOK / gridDim.x;       // gridDim.x = 32 -> 128 tokens
    const int i0 = blockIdx.x * chunk;

    for (int it = 0; it < chunk / 8; ++it) {
        const int i = i0 + it * 8 + wid;

        float t3k[8], vvv[8];
        float s2q = 0.f, s6q = 0.f, s2k = 0.f, s6k = 0.f;
#pragma unroll
        for (int j = 0; j < 8; ++j) {
            const int c = lane + 32 * j;
            const float isc = s_isc[c];
            const float qv  = qb[(size_t)i * NC + c];
            const float kx  = kb[(size_t)i * NC + c] + pos[(size_t)i * NC + c];
            const float tq  = (fmaxf(qv, 0.f) + 1e-6f) * isc;
            const float tk  = (fmaxf(kx, 0.f) + 1e-6f) * isc;
            s2q += tq * tq;
            const float tq3 = tq * tq * tq;
            s6q += tq3 * tq3;
            s2k += tk * tk;
            const float tk3 = tk * tk * tk;
            s6k += tk3 * tk3;
            t3k[j] = tk3;
            vvv[j] = vb[(size_t)i * NC + c];
        }
#pragma unroll
        for (int off = 16; off; off >>= 1) {
            s2q += __shfl_xor_sync(0xffffffffu, s2q, off);
            s6q += __shfl_xor_sync(0xffffffffu, s6q, off);
            s2k += __shfl_xor_sync(0xffffffffu, s2k, off);
            s6k += __shfl_xor_sync(0xffffffffu, s6k, off);
        }
        const float alpha_k = sqrtf(s2k / s6k);
        if (lane == 0) g_alpha[b * NTOK + i] = sqrtf(s2q / s6q);

#pragma unroll
        for (int j = 0; j < 8; ++j) {
            const int c = lane + 32 * j;
            sk[wid][c] = t3k[j] * alpha_k;
            sv[wid][c] = vvv[j];
        }
        __syncthreads();

#pragma unroll
        for (int tok = 0; tok < 8; ++tok) {
            const float kd = sk[tok][tid];          // tid == h*32+d
            accs += kd;
            const float4* v4 = (const float4*)&sv[tok][h * HD];
#pragma unroll
            for (int e4 = 0; e4 < 8; ++e4) {
                const float4 v = v4[e4];            // broadcast across lanes
                acc[e4 * 4 + 0] += kd * v.x;
                acc[e4 * 4 + 1] += kd * v.y;
                acc[e4 * 4 + 2] += kd * v.z;
                acc[e4 * 4 + 3] += kd * v.w;
            }
        }
        __syncthreads();
    }

    float* kvp = &g_kv[(((size_t)b * NHEAD + h) * HD + d) * HD];
#pragma unroll
    for (int e = 0; e < HD; ++e) atomicAdd(&kvp[e], acc[e]);
    atomicAdd(&g_ksum[((size_t)b * NHEAD + h) * HD + d], accs);
}

// ---------------------------------------------------------------------------
// Kernel 2: fused output = z * (q' @ kv) + merged 5x5 depthwise conv (LePE 3x3
// folded into per-head 5x5 dwc) + biases.
// Block = (16x16 spatial tile, head h, batch b). Lane = channel within head.
// v tile (20x20x32) staged in dynamic smem; conv reads are conflict-free
// (lanes -> consecutive channels). kv column + merged filter held in registers.
// ---------------------------------------------------------------------------
__global__ __launch_bounds__(256) void k_out(
    const float* __restrict__ qkv,
    const float* __restrict__ scale,
    const float* __restrict__ w_v,
    const float* __restrict__ b_v,
    const float* __restrict__ w_dwc,
    const float* __restrict__ b_dwc,
    float* __restrict__ out)
{
    extern __shared__ float vt[];                 // [20][20][32]

    const int tid  = threadIdx.x;
    const int lane = tid & 31;
    const int wid  = tid >> 5;
    const int b    = blockIdx.z;
    const int h    = blockIdx.y;
    const int tile = blockIdx.x;                  // 0..15
    const int r0 = (tile >> 2) * TILE;
    const int c0 = (tile & 3) * TILE;

    const float* vb = qkv + ((size_t)2 * NB + b) * NTOK * NC;
    const float* qb = qkv + (size_t)b * NTOK * NC;

    // Stage v tile (with halo 2, zero-padded at image border)
    for (int idx = tid; idx < 20 * 20 * 32; idx += 256) {
        const int e  = idx & 31;
        const int rc = idx >> 5;
        const int col = rc % 20, row = rc / 20;
        const int gy = r0 + row - 2, gx = c0 + col - 2;
        float v = 0.f;
        if (gy >= 0 && gy < RDIM && gx >= 0 && gx < RDIM)
            v = vb[(size_t)(gy * RDIM + gx) * NC + h * HD + e];
        vt[idx] = v;
    }

    // Per-lane constants in registers
    float kreg[HD];                               // kv[:, lane]
#pragma unroll
    for (int dd = 0; dd < HD; ++dd)
        kreg[dd] = g_kv[(((size_t)b * NHEAD + h) * HD + dd) * HD + lane];

    float wreg[25];                               // merged 5x5 filter for channel lane
#pragma unroll
    for (int t = 0; t < 25; ++t) {
        const int ky = t / 5, kx = t % 5;
        float w = w_dwc[lane * 25 + t];
        if (ky >= 1 && ky <= 3 && kx >= 1 && kx <= 3)
            w += w_v[(h * HD + lane) * 9 + (ky - 1) * 3 + (kx - 1)];
        wreg[t] = w;
    }

    const float my_ks   = g_ksum[((size_t)b * NHEAD + h) * HD + lane];
    const float my_isc  = 1.f / log1pf(expf(scale[h * HD + lane]));
    const float my_bias = b_v[h * HD + lane] + b_dwc[lane];

    __syncthreads();

    // Each warp: 2 rows x 16 cols of output tokens
    for (int ty = 0; ty < 2; ++ty) {
        const int lr = wid * 2 + ty;
        const int gy = r0 + lr;
        for (int lc = 0; lc < TILE; ++lc) {
            const int i = gy * RDIM + (c0 + lc);

            const float qv = qb[(size_t)i * NC + h * HD + lane];
            const float t  = (fmaxf(qv, 0.f) + 1e-6f) * my_isc;
            const float q3 = t * t * t * g_alpha[b * NTOK + i];

            // z = 1 / (q' . ksum + 1e-6)   (warp reduce)
            float zd = q3 * my_ks;
#pragma unroll
            for (int off = 16; off; off >>= 1)
                zd += __shfl_xor_sync(0xffffffffu, zd, off);
            const float z = 1.f / (zd + 1e-6f);

            // matvec: mv[lane] = sum_d q3[d] * kv[d][lane]
            float mv = 0.f;
#pragma unroll
            for (int dd = 0; dd < HD; ++dd) {
                const float qd = __shfl_sync(0xffffffffu, q3, dd);
                mv += qd * kreg[dd];
            }
            float accv = z * mv + my_bias;

            // merged 5x5 conv
#pragma unroll
            for (int ky = 0; ky < 5; ++ky) {
                const float* vr = &vt[((lr + ky) * 20 + lc) * 32 + lane];
#pragma unroll
                for (int kx = 0; kx < 5; ++kx)
                    accv += vr[kx * 32] * wreg[ky * 5 + kx];
            }

            out[(size_t)(b * NTOK + i) * NC + h * HD + lane] = accv;
        }
    }
}

// ---------------------------------------------------------------------------
extern "C" void kernel_launch(void* const* d_in, const int* in_sizes, int n_in,
                              void* d_out, int out_size)
{
    const float* qkv   = (const float*)d_in[0];
    const float* pos   = (const float*)d_in[1];
    const float* scale = (const float*)d_in[2];
    const float* w_v   = (const float*)d_in[3];
    const float* b_v   = (const float*)d_in[4];
    const float* w_dwc = (const float*)d_in[5];
    const float* b_dwc = (const float*)d_in[6];
    float* out = (float*)d_out;

    const int smem2 = 20 * 20 * 32 * sizeof(float);  // 51200 B > 48K -> opt in
    cudaFuncSetAttribute(k_out, cudaFuncAttributeMaxDynamicSharedMemorySize, smem2);

    k_zero<<<256, 256>>>();

    dim3 g1(32, NB);
    k_stats<<<g1, 256>>>(qkv, pos, scale);

    dim3 g2(16, NHEAD, NB);
    k_out<<<g2, 256, smem2>>>(qkv, scale, w_v, b_v, w_dwc, b_dwc, out);
}

// round 2
// speedup vs baseline: 1.5130x; 1.5130x over previous
#include <cuda_runtime.h>
#include <math.h>

#define NB 8
#define NTOK 4096
#define NC 256
#define NHEAD 8
#define HD 32
#define RDIM 64
#define TILE 16
#define NPART 64   // k_stats partial slots (== gridDim.x of k_stats)

// Scratch (device globals: allocation is forbidden)
__device__ float g_part[NPART * NB * NHEAD * HD * HD];   // 16 MB partial kv
__device__ float g_parts[NPART * NB * NHEAD * HD];       // partial ksum
__device__ float g_kv[NB * NHEAD * HD * HD];
__device__ float g_ksum[NB * NHEAD * HD];
__device__ float g_alpha[NB * NTOK];

// ---------------------------------------------------------------------------
// Kernel 1: focused k' + per-block kv/ksum partials + alpha_q.
// Grid (NPART, NB) x 256. Warp = token, block-wide outer-product accumulation
// with thread (h=wid, d=lane) owning kv[h][d][0..31].
// ---------------------------------------------------------------------------
__global__ __launch_bounds__(256) void k_stats(
    const float* __restrict__ qkv,
    const float* __restrict__ pos,
    const float* __restrict__ scale)
{
    __shared__ float s_isc[NC];
    __shared__ float sk[8][NC];
    __shared__ float sv[8][NC];

    const int tid  = threadIdx.x;
    const int wid  = tid >> 5;
    const int lane = tid & 31;
    const int b    = blockIdx.y;
    const int bx   = blockIdx.x;

    if (tid < NC) s_isc[tid] = 1.f / log1pf(expf(scale[tid]));
    __syncthreads();

    const float* qb = qkv + (size_t)b * NTOK * NC;
    const float* kb = qkv + ((size_t)NB + b) * NTOK * NC;
    const float* vb = qkv + ((size_t)2 * NB + b) * NTOK * NC;

    const int h = wid;
    const int d = lane;
    float acc[HD];
#pragma unroll
    for (int e = 0; e < HD; ++e) acc[e] = 0.f;
    float accs = 0.f;

    const float4 iscA = ((const float4*)s_isc)[lane];
    const float4 iscB = ((const float4*)s_isc)[lane + 32];

    const int i0 = bx * (NTOK / NPART);          // 64 tokens per block

    for (int it = 0; it < (NTOK / NPART) / 8; ++it) {
        const int i = i0 + it * 8 + wid;
        const size_t base = (size_t)i * NC;

        const float4* q4 = (const float4*)(qb + base);
        const float4* k4 = (const float4*)(kb + base);
        const float4* p4 = (const float4*)(pos + base);
        const float4* v4 = (const float4*)(vb + base);

        float4 qA = q4[lane],      qB = q4[lane + 32];
        float4 kA = k4[lane],      kB = k4[lane + 32];
        float4 pA = p4[lane],      pB = p4[lane + 32];
        float4 vA = v4[lane],      vB = v4[lane + 32];

        float s2q = 0.f, s6q = 0.f, s2k = 0.f, s6k = 0.f;
        float4 t3A, t3B;

#define PROC(qc, kc, pc, ic, outc)                                  \
        {                                                           \
            float tq = (fmaxf(qc, 0.f) + 1e-6f) * ic;               \
            float tk = (fmaxf(kc + pc, 0.f) + 1e-6f) * ic;          \
            s2q += tq * tq;                                         \
            float tq3 = tq * tq * tq; s6q += tq3 * tq3;             \
            s2k += tk * tk;                                         \
            float tk3 = tk * tk * tk; s6k += tk3 * tk3;             \
            outc = tk3;                                             \
        }
        PROC(qA.x, kA.x, pA.x, iscA.x, t3A.x)
        PROC(qA.y, kA.y, pA.y, iscA.y, t3A.y)
        PROC(qA.z, kA.z, pA.z, iscA.z, t3A.z)
        PROC(qA.w, kA.w, pA.w, iscA.w, t3A.w)
        PROC(qB.x, kB.x, pB.x, iscB.x, t3B.x)
        PROC(qB.y, kB.y, pB.y, iscB.y, t3B.y)
        PROC(qB.z, kB.z, pB.z, iscB.z, t3B.z)
        PROC(qB.w, kB.w, pB.w, iscB.w, t3B.w)
#undef PROC

#pragma unroll
        for (int off = 16; off; off >>= 1) {
            s2q += __shfl_xor_sync(0xffffffffu, s2q, off);
            s6q += __shfl_xor_sync(0xffffffffu, s6q, off);
            s2k += __shfl_xor_sync(0xffffffffu, s2k, off);
            s6k += __shfl_xor_sync(0xffffffffu, s6k, off);
        }
        const float ak = sqrtf(s2k / s6k);
        if (lane == 0) g_alpha[b * NTOK + i] = sqrtf(s2q / s6q);

        float4* skp = (float4*)&sk[wid][0];
        float4* svp = (float4*)&sv[wid][0];
        skp[lane]      = make_float4(t3A.x * ak, t3A.y * ak, t3A.z * ak, t3A.w * ak);
        skp[lane + 32] = make_float4(t3B.x * ak, t3B.y * ak, t3B.z * ak, t3B.w * ak);
        svp[lane]      = vA;
        svp[lane + 32] = vB;
        __syncthreads();

#pragma unroll
        for (int tok = 0; tok < 8; ++tok) {
            const float kd = sk[tok][tid];
            accs += kd;
            const float4* vv = (const float4*)&sv[tok][h * HD];
#pragma unroll
            for (int e4 = 0; e4 < 8; ++e4) {
                const float4 v = vv[e4];
                acc[e4 * 4 + 0] += kd * v.x;
                acc[e4 * 4 + 1] += kd * v.y;
                acc[e4 * 4 + 2] += kd * v.z;
                acc[e4 * 4 + 3] += kd * v.w;
            }
        }
        __syncthreads();
    }

    // Write partials (no atomics, no pre-zeroing)
    float4* dst = (float4*)&g_part[((((size_t)bx * NB + b) * NHEAD + h) * HD + d) * HD];
#pragma unroll
    for (int e4 = 0; e4 < 8; ++e4)
        dst[e4] = make_float4(acc[e4 * 4], acc[e4 * 4 + 1], acc[e4 * 4 + 2], acc[e4 * 4 + 3]);
    g_parts[(((size_t)bx * NB + b) * NHEAD + h) * HD + d] = accs;
}

// ---------------------------------------------------------------------------
// Kernel 2: reduce NPART partials -> g_kv, g_ksum.
// Grid 256 = (b*h, quarter); thread = one kv element, sums 64 partials.
// ---------------------------------------------------------------------------
__global__ __launch_bounds__(256) void k_reduce()
{
    const int tid = threadIdx.x;
    const int bh  = blockIdx.x >> 2;
    const int qtr = blockIdx.x & 3;
    const int entry = qtr * 256 + tid;

    float s = 0.f;
#pragma unroll 8
    for (int p = 0; p < NPART; ++p)
        s += g_part[((size_t)p * NB * NHEAD + bh) * (HD * HD) + entry];
    g_kv[(size_t)bh * HD * HD + entry] = s;

    if (qtr == 0 && tid < HD) {
        float ss = 0.f;
#pragma unroll 8
        for (int p = 0; p < NPART; ++p)
            ss += g_parts[((size_t)p * NB * NHEAD + bh) * HD + tid];
        g_ksum[(size_t)bh * HD + tid] = ss;
    }
}

// ---------------------------------------------------------------------------
// Kernel 3: fused output. Block = (16x16 tile, head, batch). Lane = channel.
// Phase A: stage v tile (halo 2) + q3 (focused q) into smem.
// Phase B: all 256 z-values in parallel (thread = token).
// Phase C: matvec via broadcast LDS.128 + merged 5x5 conv (sliding window).
// ---------------------------------------------------------------------------
#define VT_OFF   0
#define Q3_OFF   (20 * 20 * 32)                 // 12800
#define Q3_PITCH 36
#define ZS_OFF   (Q3_OFF + 256 * Q3_PITCH)      // 22016
#define KS_OFF   (ZS_OFF + 256)                 // 22272
#define SMEM_FLOATS (KS_OFF + 32)               // 22304

__global__ __launch_bounds__(256, 2) void k_out(
    const float* __restrict__ qkv,
    const float* __restrict__ scale,
    const float* __restrict__ w_v,
    const float* __restrict__ b_v,
    const float* __restrict__ w_dwc,
    const float* __restrict__ b_dwc,
    float* __restrict__ out)
{
    extern __shared__ float sm[];
    float* vt  = sm + VT_OFF;
    float* q3s = sm + Q3_OFF;
    float* zs  = sm + ZS_OFF;
    float* ks  = sm + KS_OFF;

    const int tid  = threadIdx.x;
    const int lane = tid & 31;
    const int wid  = tid >> 5;
    const int b    = blockIdx.z;
    const int h    = blockIdx.y;
    const int tile = blockIdx.x;
    const int r0 = (tile >> 2) * TILE;
    const int c0 = (tile & 3) * TILE;

    const float* vb = qkv + ((size_t)2 * NB + b) * NTOK * NC;
    const float* qb = qkv + (size_t)b * NTOK * NC;

    // kv column + merged filter + per-lane consts (overlap with staging)
    float kreg[HD];
#pragma unroll
    for (int dd = 0; dd < HD; ++dd)
        kreg[dd] = g_kv[(((size_t)b * NHEAD + h) * HD + dd) * HD + lane];

    float wreg[25];
#pragma unroll
    for (int t = 0; t < 25; ++t) {
        const int ky = t / 5, kx = t % 5;
        float w = w_dwc[lane * 25 + t];
        if (ky >= 1 && ky <= 3 && kx >= 1 && kx <= 3)
            w += w_v[(h * HD + lane) * 9 + (ky - 1) * 3 + (kx - 1)];
        wreg[t] = w;
    }
    const float my_isc  = 1.f / log1pf(expf(scale[h * HD + lane]));
    const float my_bias = b_v[h * HD + lane] + b_dwc[lane];

    // Phase A: v tile with halo (float4)
    for (int idx = tid; idx < 20 * 20 * 8; idx += 256) {
        const int e4 = idx & 7;
        const int rc = idx >> 3;
        const int col = rc % 20, row = rc / 20;
        const int gy = r0 + row - 2, gx = c0 + col - 2;
        float4 v = make_float4(0.f, 0.f, 0.f, 0.f);
        if (gy >= 0 && gy < RDIM && gx >= 0 && gx < RDIM)
            v = *(const float4*)&vb[(size_t)(gy * RDIM + gx) * NC + h * HD + e4 * 4];
        ((float4*)vt)[idx] = v;
    }

    // Phase A2: focused q3 tile (each warp: 2 rows x 16 cols)
#pragma unroll
    for (int ty = 0; ty < 2; ++ty) {
        const int lr = wid * 2 + ty;
        const int gy = r0 + lr;
        for (int lc = 0; lc < TILE; ++lc) {
            const int i = gy * RDIM + (c0 + lc);
            const float qv = qb[(size_t)i * NC + h * HD + lane];
            const float t  = (fmaxf(qv, 0.f) + 1e-6f) * my_isc;
            const float a  = g_alpha[b * NTOK + i];
            q3s[(lr * TILE + lc) * Q3_PITCH + lane] = t * t * t * a;
        }
    }
    if (tid < HD) ks[tid] = g_ksum[((size_t)b * NHEAD + h) * HD + tid];
    __syncthreads();

    // Phase B: z for all 256 tokens in parallel (thread = token)
    {
        float zd = 0.f;
#pragma unroll
        for (int k4 = 0; k4 < 8; ++k4) {
            const float4 q = *(const float4*)&q3s[tid * Q3_PITCH + 4 * k4];
            const float4 kk = *(const float4*)&ks[4 * k4];
            zd += q.x * kk.x + q.y * kk.y + q.z * kk.z + q.w * kk.w;
        }
        zs[tid] = 1.f / (zd + 1e-6f);
    }
    __syncthreads();

    // Phase C: matvec + conv
#pragma unroll
    for (int ty = 0; ty < 2; ++ty) {
        const int lr = wid * 2 + ty;
        const int gy = r0 + lr;

        float ring[5][5];                        // [slot][ky]
#pragma unroll
        for (int s = 0; s < 4; ++s)
#pragma unroll
            for (int ky = 0; ky < 5; ++ky)
                ring[s][ky] = vt[((lr + ky) * 20 + s) * 32 + lane];

#pragma unroll
        for (int lc = 0; lc < TILE; ++lc) {
            const int slot = (lc + 4) % 5;
#pragma unroll
            for (int ky = 0; ky < 5; ++ky)
                ring[slot][ky] = vt[((lr + ky) * 20 + lc + 4) * 32 + lane];

            const int ltok = lr * TILE + lc;

            float mv0 = 0.f, mv1 = 0.f;
#pragma unroll
            for (int k4 = 0; k4 < 8; ++k4) {
                const float4 q = *(const float4*)&q3s[ltok * Q3_PITCH + 4 * k4];
                mv0 += q.x * kreg[4 * k4 + 0] + q.z * kreg[4 * k4 + 2];
                mv1 += q.y * kreg[4 * k4 + 1] + q.w * kreg[4 * k4 + 3];
            }
            float accv = zs[ltok] * (mv0 + mv1) + my_bias;

#pragma unroll
            for (int ky = 0; ky < 5; ++ky)
#pragma unroll
                for (int kx = 0; kx < 5; ++kx)
                    accv += ring[(lc + kx) % 5][ky] * wreg[ky * 5 + kx];

            const int i = gy * RDIM + (c0 + lc);
            out[(size_t)(b * NTOK + i) * NC + h * HD + lane] = accv;
        }
    }
}

// ---------------------------------------------------------------------------
extern "C" void kernel_launch(void* const* d_in, const int* in_sizes, int n_in,
                              void* d_out, int out_size)
{
    const float* qkv   = (const float*)d_in[0];
    const float* pos   = (const float*)d_in[1];
    const float* scale = (const float*)d_in[2];
    const float* w_v   = (const float*)d_in[3];
    const float* b_v   = (const float*)d_in[4];
    const float* w_dwc = (const float*)d_in[5];
    const float* b_dwc = (const float*)d_in[6];
    float* out = (float*)d_out;

    const int smem2 = SMEM_FLOATS * sizeof(float);   // 89216 B
    cudaFuncSetAttribute(k_out, cudaFuncAttributeMaxDynamicSharedMemorySize, smem2);

    dim3 g1(NPART, NB);
    k_stats<<<g1, 256>>>(qkv, pos, scale);

    k_reduce<<<256, 256>>>();

    dim3 g2(16, NHEAD, NB);
    k_out<<<g2, 256, smem2>>>(qkv, scale, w_v, b_v, w_dwc, b_dwc, out);
}

// round 3
// speedup vs baseline: 1.8917x; 1.2503x over previous
#include <cuda_runtime.h>
#include <math.h>

#define NB 8
#define NTOK 4096
#define NC 256
#define NHEAD 8
#define HD 32
#define RDIM 64
#define TILE 16
#define NPART 32   // k_stats partial slots (== gridDim.x of k_stats)

// Scratch (device globals: allocation is forbidden)
__device__ float g_part[NPART * NB * NHEAD * HD * HD];   // 8 MB partial kv
__device__ float g_parts[NPART * NB * NHEAD * HD];       // partial ksum
__device__ float g_kv[NB * NHEAD * HD * HD];
__device__ float g_ksum[NB * NHEAD * HD];
__device__ float g_alpha[NB * NTOK];

// ---------------------------------------------------------------------------
// Kernel 1: focused k' + per-block kv/ksum partials + alpha_q.
// Grid (NPART, NB) x 256. Warp = token, block-wide outer-product accumulation
// with thread (h=wid, d=lane) owning kv[h][d][0..31].
// ---------------------------------------------------------------------------
__global__ __launch_bounds__(256, 3) void k_stats(
    const float* __restrict__ qkv,
    const float* __restrict__ pos,
    const float* __restrict__ scale)
{
    __shared__ float s_isc[NC];
    __shared__ float sk[8][NC];
    __shared__ float sv[8][NC];

    const int tid  = threadIdx.x;
    const int wid  = tid >> 5;
    const int lane = tid & 31;
    const int b    = blockIdx.y;
    const int bx   = blockIdx.x;

    if (tid < NC) s_isc[tid] = 1.f / log1pf(expf(scale[tid]));
    __syncthreads();

    const float* qb = qkv + (size_t)b * NTOK * NC;
    const float* kb = qkv + ((size_t)NB + b) * NTOK * NC;
    const float* vb = qkv + ((size_t)2 * NB + b) * NTOK * NC;

    const int h = wid;
    const int d = lane;
    float acc[HD];
#pragma unroll
    for (int e = 0; e < HD; ++e) acc[e] = 0.f;
    float accs = 0.f;

    const float4 iscA = ((const float4*)s_isc)[lane];
    const float4 iscB = ((const float4*)s_isc)[lane + 32];

    const int i0 = bx * (NTOK / NPART);          // 128 tokens per block

    for (int it = 0; it < (NTOK / NPART) / 8; ++it) {
        const int i = i0 + it * 8 + wid;
        const size_t base = (size_t)i * NC;

        const float4* q4 = (const float4*)(qb + base);
        const float4* k4 = (const float4*)(kb + base);
        const float4* p4 = (const float4*)(pos + base);
        const float4* v4 = (const float4*)(vb + base);

        float4 qA = q4[lane],      qB = q4[lane + 32];
        float4 kA = k4[lane],      kB = k4[lane + 32];
        float4 pA = p4[lane],      pB = p4[lane + 32];
        float4 vA = v4[lane],      vB = v4[lane + 32];

        float s2q = 0.f, s6q = 0.f, s2k = 0.f, s6k = 0.f;
        float4 t3A, t3B;

#define PROC(qc, kc, pc, ic, outc)                                  \
        {                                                           \
            float tq = (fmaxf(qc, 0.f) + 1e-6f) * ic;               \
            float tk = (fmaxf(kc + pc, 0.f) + 1e-6f) * ic;          \
            s2q += tq * tq;                                         \
            float tq3 = tq * tq * tq; s6q += tq3 * tq3;             \
            s2k += tk * tk;                                         \
            float tk3 = tk * tk * tk; s6k += tk3 * tk3;             \
            outc = tk3;                                             \
        }
        PROC(qA.x, kA.x, pA.x, iscA.x, t3A.x)
        PROC(qA.y, kA.y, pA.y, iscA.y, t3A.y)
        PROC(qA.z, kA.z, pA.z, iscA.z, t3A.z)
        PROC(qA.w, kA.w, pA.w, iscA.w, t3A.w)
        PROC(qB.x, kB.x, pB.x, iscB.x, t3B.x)
        PROC(qB.y, kB.y, pB.y, iscB.y, t3B.y)
        PROC(qB.z, kB.z, pB.z, iscB.z, t3B.z)
        PROC(qB.w, kB.w, pB.w, iscB.w, t3B.w)
#undef PROC

#pragma unroll
        for (int off = 16; off; off >>= 1) {
            s2q += __shfl_xor_sync(0xffffffffu, s2q, off);
            s6q += __shfl_xor_sync(0xffffffffu, s6q, off);
            s2k += __shfl_xor_sync(0xffffffffu, s2k, off);
            s6k += __shfl_xor_sync(0xffffffffu, s6k, off);
        }
        const float ak = sqrtf(s2k / s6k);
        if (lane == 0) g_alpha[b * NTOK + i] = sqrtf(s2q / s6q);

        float4* skp = (float4*)&sk[wid][0];
        float4* svp = (float4*)&sv[wid][0];
        skp[lane]      = make_float4(t3A.x * ak, t3A.y * ak, t3A.z * ak, t3A.w * ak);
        skp[lane + 32] = make_float4(t3B.x * ak, t3B.y * ak, t3B.z * ak, t3B.w * ak);
        svp[lane]      = vA;
        svp[lane + 32] = vB;
        __syncthreads();

        // Hoisted kd loads, then the rank-8 outer-product update
        float kd[8];
#pragma unroll
        for (int tok = 0; tok < 8; ++tok) {
            kd[tok] = sk[tok][tid];
            accs += kd[tok];
        }
#pragma unroll
        for (int tok = 0; tok < 8; ++tok) {
            const float4* vv = (const float4*)&sv[tok][h * HD];
#pragma unroll
            for (int e4 = 0; e4 < 8; ++e4) {
                const float4 v = vv[e4];
                acc[e4 * 4 + 0] += kd[tok] * v.x;
                acc[e4 * 4 + 1] += kd[tok] * v.y;
                acc[e4 * 4 + 2] += kd[tok] * v.z;
                acc[e4 * 4 + 3] += kd[tok] * v.w;
            }
        }
        __syncthreads();
    }

    // Write partials (no atomics, no pre-zeroing)
    float4* dst = (float4*)&g_part[((((size_t)bx * NB + b) * NHEAD + h) * HD + d) * HD];
#pragma unroll
    for (int e4 = 0; e4 < 8; ++e4)
        dst[e4] = make_float4(acc[e4 * 4], acc[e4 * 4 + 1], acc[e4 * 4 + 2], acc[e4 * 4 + 3]);
    g_parts[(((size_t)bx * NB + b) * NHEAD + h) * HD + d] = accs;
}

// ---------------------------------------------------------------------------
// Kernel 2: reduce NPART partials -> g_kv, g_ksum.
// ---------------------------------------------------------------------------
__global__ __launch_bounds__(256) void k_reduce()
{
    const int tid = threadIdx.x;
    const int bh  = blockIdx.x >> 2;
    const int qtr = blockIdx.x & 3;
    const int entry = qtr * 256 + tid;

    float s = 0.f;
#pragma unroll 8
    for (int p = 0; p < NPART; ++p)
        s += g_part[((size_t)p * NB * NHEAD + bh) * (HD * HD) + entry];
    g_kv[(size_t)bh * HD * HD + entry] = s;

    if (qtr == 0 && tid < HD) {
        float ss = 0.f;
#pragma unroll 8
        for (int p = 0; p < NPART; ++p)
            ss += g_parts[((size_t)p * NB * NHEAD + bh) * HD + tid];
        g_ksum[(size_t)bh * HD + tid] = ss;
    }
}

// ---------------------------------------------------------------------------
// Kernel 3: fused output. Block = (16x16 tile, head, batch). Lane = channel.
// ---------------------------------------------------------------------------
#define VT_OFF   0
#define Q3_OFF   (20 * 20 * 32)                 // 12800
#define Q3_PITCH 36
#define ZS_OFF   (Q3_OFF + 256 * Q3_PITCH)      // 22016
#define KS_OFF   (ZS_OFF + 256)                 // 22272
#define SMEM_FLOATS (KS_OFF + 32)               // 22304

__global__ __launch_bounds__(256, 2) void k_out(
    const float* __restrict__ qkv,
    const float* __restrict__ scale,
    const float* __restrict__ w_v,
    const float* __restrict__ b_v,
    const float* __restrict__ w_dwc,
    const float* __restrict__ b_dwc,
    float* __restrict__ out)
{
    extern __shared__ float sm[];
    float* vt  = sm + VT_OFF;
    float* q3s = sm + Q3_OFF;
    float* zs  = sm + ZS_OFF;
    float* ks  = sm + KS_OFF;

    const int tid  = threadIdx.x;
    const int lane = tid & 31;
    const int wid  = tid >> 5;
    const int b    = blockIdx.z;
    const int h    = blockIdx.y;
    const int tile = blockIdx.x;
    const int r0 = (tile >> 2) * TILE;
    const int c0 = (tile & 3) * TILE;

    const float* vb = qkv + ((size_t)2 * NB + b) * NTOK * NC;
    const float* qb = qkv + (size_t)b * NTOK * NC;

    // Phase A: v tile with halo — 13 predicated, fully unrolled slots so all
    // LDG.128s issue back-to-back (MLP ~13) before any dependent STS.
#pragma unroll
    for (int u = 0; u < 13; ++u) {
        const int idx = tid + u * 256;
        if (idx < 20 * 20 * 8) {
            const int e4 = idx & 7;
            const int rc = idx >> 3;
            const int col = rc % 20, row = rc / 20;
            const int gy = r0 + row - 2, gx = c0 + col - 2;
            float4 v = make_float4(0.f, 0.f, 0.f, 0.f);
            if (gy >= 0 && gy < RDIM && gx >= 0 && gx < RDIM)
                v = *(const float4*)&vb[(size_t)(gy * RDIM + gx) * NC + h * HD + e4 * 4];
            ((float4*)vt)[idx] = v;
        }
    }

    // Per-lane constants (these LDGs overlap the v-tile loads above)
    float kreg[HD];
#pragma unroll
    for (int dd = 0; dd < HD; ++dd)
        kreg[dd] = g_kv[(((size_t)b * NHEAD + h) * HD + dd) * HD + lane];

    float wreg[25];
#pragma unroll
    for (int t = 0; t < 25; ++t) {
        const int ky = t / 5, kx = t % 5;
        float w = w_dwc[lane * 25 + t];
        if (ky >= 1 && ky <= 3 && kx >= 1 && kx <= 3)
            w += w_v[(h * HD + lane) * 9 + (ky - 1) * 3 + (kx - 1)];
        wreg[t] = w;
    }
    const float my_isc  = 1.f / log1pf(expf(scale[h * HD + lane]));
    const float my_bias = b_v[h * HD + lane] + b_dwc[lane];

    // Phase A2: focused q3 tile — batch ALL 16 token loads per row before the
    // dependent math (kills the LDG->STS serial chain).
#pragma unroll
    for (int ty = 0; ty < 2; ++ty) {
        const int lr = wid * 2 + ty;
        const int gy = r0 + lr;
        float qv[TILE], al[TILE];
#pragma unroll
        for (int lc = 0; lc < TILE; ++lc) {
            const int i = gy * RDIM + (c0 + lc);
            qv[lc] = qb[(size_t)i * NC + h * HD + lane];
            al[lc] = g_alpha[b * NTOK + i];
        }
#pragma unroll
        for (int lc = 0; lc < TILE; ++lc) {
            const float t = (fmaxf(qv[lc], 0.f) + 1e-6f) * my_isc;
            q3s[(lr * TILE + lc) * Q3_PITCH + lane] = t * t * t * al[lc];
        }
    }
    if (tid < HD) ks[tid] = g_ksum[((size_t)b * NHEAD + h) * HD + tid];
    __syncthreads();

    // Phase B: z for all 256 tokens in parallel (thread = token)
    {
        float zd = 0.f;
#pragma unroll
        for (int k4 = 0; k4 < 8; ++k4) {
            const float4 q = *(const float4*)&q3s[tid * Q3_PITCH + 4 * k4];
            const float4 kk = *(const float4*)&ks[4 * k4];
            zd += q.x * kk.x + q.y * kk.y + q.z * kk.z + q.w * kk.w;
        }
        zs[tid] = 1.f / (zd + 1e-6f);
    }
    __syncthreads();

    // Phase C: matvec + merged 5x5 conv (sliding register window)
#pragma unroll
    for (int ty = 0; ty < 2; ++ty) {
        const int lr = wid * 2 + ty;
        const int gy = r0 + lr;

        float ring[5][5];                        // [slot][ky]
#pragma unroll
        for (int s = 0; s < 4; ++s)
#pragma unroll
            for (int ky = 0; ky < 5; ++ky)
                ring[s][ky] = vt[((lr + ky) * 20 + s) * 32 + lane];

#pragma unroll
        for (int lc = 0; lc < TILE; ++lc) {
            const int slot = (lc + 4) % 5;
#pragma unroll
            for (int ky = 0; ky < 5; ++ky)
                ring[slot][ky] = vt[((lr + ky) * 20 + lc + 4) * 32 + lane];

            const int ltok = lr * TILE + lc;

            float mv0 = 0.f, mv1 = 0.f;
#pragma unroll
            for (int k4 = 0; k4 < 8; ++k4) {
                const float4 q = *(const float4*)&q3s[ltok * Q3_PITCH + 4 * k4];
                mv0 += q.x * kreg[4 * k4 + 0] + q.z * kreg[4 * k4 + 2];
                mv1 += q.y * kreg[4 * k4 + 1] + q.w * kreg[4 * k4 + 3];
            }
            float accv = zs[ltok] * (mv0 + mv1) + my_bias;

#pragma unroll
            for (int ky = 0; ky < 5; ++ky)
#pragma unroll
                for (int kx = 0; kx < 5; ++kx)
                    accv += ring[(lc + kx) % 5][ky] * wreg[ky * 5 + kx];

            const int i = gy * RDIM + (c0 + lc);
            out[(size_t)(b * NTOK + i) * NC + h * HD + lane] = accv;
        }
    }
}

// ---------------------------------------------------------------------------
extern "C" void kernel_launch(void* const* d_in, const int* in_sizes, int n_in,
                              void* d_out, int out_size)
{
    const float* qkv   = (const float*)d_in[0];
    const float* pos   = (const float*)d_in[1];
    const float* scale = (const float*)d_in[2];
    const float* w_v   = (const float*)d_in[3];
    const float* b_v   = (const float*)d_in[4];
    const float* w_dwc = (const float*)d_in[5];
    const float* b_dwc = (const float*)d_in[6];
    float* out = (float*)d_out;

    const int smem2 = SMEM_FLOATS * sizeof(float);   // 89216 B
    cudaFuncSetAttribute(k_out, cudaFuncAttributeMaxDynamicSharedMemorySize, smem2);

    dim3 g1(NPART, NB);
    k_stats<<<g1, 256>>>(qkv, pos, scale);

    k_reduce<<<256, 256>>>();

    dim3 g2(16, NHEAD, NB);
    k_out<<<g2, 256, smem2>>>(qkv, scale, w_v, b_v, w_dwc, b_dwc, out);
}

// round 4
// speedup vs baseline: 1.9721x; 1.0425x over previous
#include <cuda_runtime.h>
#include <math.h>

#define NB 8
#define NTOK 4096
#define NC 256
#define NHEAD 8
#define HD 32
#define RDIM 64
#define TILE 16
#define NPART 32

// Scratch (device globals: allocation is forbidden)
__device__ float g_part[NPART * NB * NHEAD * HD * HD];   // 8 MB partial kv
__device__ float g_parts[NPART * NB * NHEAD * HD];
__device__ float g_kv[NB * NHEAD * HD * HD];
__device__ float g_ksum[NB * NHEAD * HD];
__device__ float g_alpha[NB * NTOK];

// ---------------------------------------------------------------------------
// Kernel 1: focused k' + kv/ksum partials + alpha_q.
// 512 threads = 16 warps. Warp = token. Outer-product ownership split:
// h = wid>>1, e-half = wid&1, d = lane -> acc[16]. Single wave, ~43% occ.
// ---------------------------------------------------------------------------
__global__ __launch_bounds__(512, 2) void k_stats(
    const float* __restrict__ qkv,
    const float* __restrict__ pos,
    const float* __restrict__ scale)
{
    __shared__ float s_isc[NC];
    __shared__ float sk[16][NC];
    __shared__ float sv[16][NC];

    const int tid  = threadIdx.x;
    const int wid  = tid >> 5;
    const int lane = tid & 31;
    const int b    = blockIdx.y;
    const int bx   = blockIdx.x;

    if (tid < NC) s_isc[tid] = 1.f / log1pf(expf(scale[tid]));
    __syncthreads();

    const float* qb = qkv + (size_t)b * NTOK * NC;
    const float* kb = qkv + ((size_t)NB + b) * NTOK * NC;
    const float* vb = qkv + ((size_t)2 * NB + b) * NTOK * NC;

    const int h    = wid >> 1;
    const int half = wid & 1;
    const int d    = lane;

    float acc[16];
#pragma unroll
    for (int e = 0; e < 16; ++e) acc[e] = 0.f;
    float accs = 0.f;

    const float4 iscA = ((const float4*)s_isc)[lane];
    const float4 iscB = ((const float4*)s_isc)[lane + 32];

    const int i0 = bx * (NTOK / NPART);          // 128 tokens per block

    for (int it = 0; it < (NTOK / NPART) / 16; ++it) {
        const int i = i0 + it * 16 + wid;
        const size_t base = (size_t)i * NC;

        const float4* q4 = (const float4*)(qb + base);
        const float4* k4 = (const float4*)(kb + base);
        const float4* p4 = (const float4*)(pos + base);
        const float4* v4 = (const float4*)(vb + base);

        float4 qA = q4[lane],      qB = q4[lane + 32];
        float4 kA = k4[lane],      kB = k4[lane + 32];
        float4 pA = p4[lane],      pB = p4[lane + 32];
        float4 vA = v4[lane],      vB = v4[lane + 32];

        float s2q = 0.f, s6q = 0.f, s2k = 0.f, s6k = 0.f;
        float4 t3A, t3B;

#define PROC(qc, kc, pc, ic, outc)                                  \
        {                                                           \
            float tq = (fmaxf(qc, 0.f) + 1e-6f) * ic;               \
            float tk = (fmaxf(kc + pc, 0.f) + 1e-6f) * ic;          \
            s2q += tq * tq;                                         \
            float tq3 = tq * tq * tq; s6q += tq3 * tq3;             \
            s2k += tk * tk;                                         \
            float tk3 = tk * tk * tk; s6k += tk3 * tk3;             \
            outc = tk3;                                             \
        }
        PROC(qA.x, kA.x, pA.x, iscA.x, t3A.x)
        PROC(qA.y, kA.y, pA.y, iscA.y, t3A.y)
        PROC(qA.z, kA.z, pA.z, iscA.z, t3A.z)
        PROC(qA.w, kA.w, pA.w, iscA.w, t3A.w)
        PROC(qB.x, kB.x, pB.x, iscB.x, t3B.x)
        PROC(qB.y, kB.y, pB.y, iscB.y, t3B.y)
        PROC(qB.z, kB.z, pB.z, iscB.z, t3B.z)
        PROC(qB.w, kB.w, pB.w, iscB.w, t3B.w)
#undef PROC

#pragma unroll
        for (int off = 16; off; off >>= 1) {
            s2q += __shfl_xor_sync(0xffffffffu, s2q, off);
            s6q += __shfl_xor_sync(0xffffffffu, s6q, off);
            s2k += __shfl_xor_sync(0xffffffffu, s2k, off);
            s6k += __shfl_xor_sync(0xffffffffu, s6k, off);
        }
        const float ak = sqrtf(s2k / s6k);
        if (lane == 0) g_alpha[b * NTOK + i] = sqrtf(s2q / s6q);

        float4* skp = (float4*)&sk[wid][0];
        float4* svp = (float4*)&sv[wid][0];
        skp[lane]      = make_float4(t3A.x * ak, t3A.y * ak, t3A.z * ak, t3A.w * ak);
        skp[lane + 32] = make_float4(t3B.x * ak, t3B.y * ak, t3B.z * ak, t3B.w * ak);
        svp[lane]      = vA;
        svp[lane + 32] = vB;
        __syncthreads();

#pragma unroll
        for (int c = 0; c < 2; ++c) {
            float kd[8];
#pragma unroll
            for (int t8 = 0; t8 < 8; ++t8) {
                kd[t8] = sk[c * 8 + t8][h * HD + d];
                accs += kd[t8];
            }
#pragma unroll
            for (int t8 = 0; t8 < 8; ++t8) {
                const float4* vv = (const float4*)&sv[c * 8 + t8][h * HD + half * 16];
#pragma unroll
                for (int e4 = 0; e4 < 4; ++e4) {
                    const float4 v = vv[e4];
                    acc[e4 * 4 + 0] += kd[t8] * v.x;
                    acc[e4 * 4 + 1] += kd[t8] * v.y;
                    acc[e4 * 4 + 2] += kd[t8] * v.z;
                    acc[e4 * 4 + 3] += kd[t8] * v.w;
                }
            }
        }
        __syncthreads();
    }

    // Layout identical to before: [bx][b][h][d][e], halves write e-ranges.
    float4* dst = (float4*)&g_part[((((size_t)bx * NB + b) * NHEAD + h) * HD + d) * HD + half * 16];
#pragma unroll
    for (int e4 = 0; e4 < 4; ++e4)
        dst[e4] = make_float4(acc[e4 * 4], acc[e4 * 4 + 1], acc[e4 * 4 + 2], acc[e4 * 4 + 3]);
    if (half == 0)
        g_parts[(((size_t)bx * NB + b) * NHEAD + h) * HD + d] = accs;
}

// ---------------------------------------------------------------------------
// Kernel 2: reduce NPART partials -> g_kv, g_ksum.
// ---------------------------------------------------------------------------
__global__ __launch_bounds__(256) void k_reduce()
{
    const int tid = threadIdx.x;
    const int bh  = blockIdx.x >> 2;
    const int qtr = blockIdx.x & 3;
    const int entry = qtr * 256 + tid;

    float s = 0.f;
#pragma unroll 8
    for (int p = 0; p < NPART; ++p)
        s += g_part[((size_t)p * NB * NHEAD + bh) * (HD * HD) + entry];
    g_kv[(size_t)bh * HD * HD + entry] = s;

    if (qtr == 0 && tid < HD) {
        float ss = 0.f;
#pragma unroll 8
        for (int p = 0; p < NPART; ++p)
            ss += g_parts[((size_t)p * NB * NHEAD + bh) * HD + tid];
        g_ksum[(size_t)bh * HD + tid] = ss;
    }
}

// ---------------------------------------------------------------------------
// Kernel 3: merged 5x5 depthwise conv (LePE folded in) + bias -> writes out.
// Block = (16x16 tile, head, batch), lane = channel. vt-only smem (51 KB).
// ---------------------------------------------------------------------------
__global__ __launch_bounds__(256, 3) void k_conv(
    const float* __restrict__ qkv,
    const float* __restrict__ w_v,
    const float* __restrict__ b_v,
    const float* __restrict__ w_dwc,
    const float* __restrict__ b_dwc,
    float* __restrict__ out)
{
    extern __shared__ float vt[];                 // [20][20][32]

    const int tid  = threadIdx.x;
    const int lane = tid & 31;
    const int wid  = tid >> 5;
    const int b    = blockIdx.z;
    const int h    = blockIdx.y;
    const int tile = blockIdx.x;
    const int r0 = (tile >> 2) * TILE;
    const int c0 = (tile & 3) * TILE;

    const float* vb = qkv + ((size_t)2 * NB + b) * NTOK * NC;

    // Stage v tile with halo (13 predicated slots, all LDG.128 batched)
#pragma unroll
    for (int u = 0; u < 13; ++u) {
        const int idx = tid + u * 256;
        if (idx < 20 * 20 * 8) {
            const int e4 = idx & 7;
            const int rc = idx >> 3;
            const int col = rc % 20, row = rc / 20;
            const int gy = r0 + row - 2, gx = c0 + col - 2;
            float4 v = make_float4(0.f, 0.f, 0.f, 0.f);
            if (gy >= 0 && gy < RDIM && gx >= 0 && gx < RDIM)
                v = *(const float4*)&vb[(size_t)(gy * RDIM + gx) * NC + h * HD + e4 * 4];
            ((float4*)vt)[idx] = v;
        }
    }

    float wreg[25];
#pragma unroll
    for (int t = 0; t < 25; ++t) {
        const int ky = t / 5, kx = t % 5;
        float w = w_dwc[lane * 25 + t];
        if (ky >= 1 && ky <= 3 && kx >= 1 && kx <= 3)
            w += w_v[(h * HD + lane) * 9 + (ky - 1) * 3 + (kx - 1)];
        wreg[t] = w;
    }
    const float my_bias = b_v[h * HD + lane] + b_dwc[lane];
    __syncthreads();

#pragma unroll
    for (int ty = 0; ty < 2; ++ty) {
        const int lr = wid * 2 + ty;
        const int gy = r0 + lr;

        float ring[5][5];
#pragma unroll
        for (int s = 0; s < 4; ++s)
#pragma unroll
            for (int ky = 0; ky < 5; ++ky)
                ring[s][ky] = vt[((lr + ky) * 20 + s) * 32 + lane];

#pragma unroll
        for (int lc = 0; lc < TILE; ++lc) {
            const int slot = (lc + 4) % 5;
#pragma unroll
            for (int ky = 0; ky < 5; ++ky)
                ring[slot][ky] = vt[((lr + ky) * 20 + lc + 4) * 32 + lane];

            float accv = my_bias;
#pragma unroll
            for (int ky = 0; ky < 5; ++ky)
#pragma unroll
                for (int kx = 0; kx < 5; ++kx)
                    accv += ring[(lc + kx) % 5][ky] * wreg[ky * 5 + kx];

            const int i = gy * RDIM + (c0 + lc);
            out[(size_t)(b * NTOK + i) * NC + h * HD + lane] = accv;
        }
    }
}

// ---------------------------------------------------------------------------
// Kernel 4: attention term, out += z * (q3 @ kv). Linear token blocks,
// q3s-only smem (~40 KB), 4 CTAs/SM. out read hits L2 (just written by k_conv).
// ---------------------------------------------------------------------------
#define QP 36   // q3s pitch (4-float4-aligned, conflict-free in phase B)

__global__ __launch_bounds__(256, 4) void k_attn(
    const float* __restrict__ qkv,
    const float* __restrict__ scale,
    float* __restrict__ out)
{
    __shared__ float q3s[256 * QP];
    __shared__ float a_s[256];
    __shared__ float zs[256];
    __shared__ float ks[HD];

    const int tid  = threadIdx.x;
    const int lane = tid & 31;
    const int wid  = tid >> 5;
    const int b    = blockIdx.z;
    const int h    = blockIdx.y;

    const float* qb = qkv + (size_t)b * NTOK * NC;

    float kreg[HD];
#pragma unroll
    for (int dd = 0; dd < HD; ++dd)
        kreg[dd] = g_kv[(((size_t)b * NHEAD + h) * HD + dd) * HD + lane];
    const float my_isc = 1.f / log1pf(expf(scale[h * HD + lane]));
    if (tid < HD) ks[tid] = g_ksum[((size_t)b * NHEAD + h) * HD + tid];

    for (int s = 0; s < 2; ++s) {
        const int s0 = blockIdx.x * 512 + s * 256;

        a_s[tid] = g_alpha[b * NTOK + s0 + tid];
        __syncthreads();

        // Phase A: focused q3 for warp's 32 tokens (2 chunks of 16 batched LDGs)
#pragma unroll
        for (int c = 0; c < 2; ++c) {
            float qv[16];
#pragma unroll
            for (int j = 0; j < 16; ++j) {
                const int lt = wid * 32 + c * 16 + j;
                qv[j] = qb[(size_t)(s0 + lt) * NC + h * HD + lane];
            }
#pragma unroll
            for (int j = 0; j < 16; ++j) {
                const int lt = wid * 32 + c * 16 + j;
                const float t = (fmaxf(qv[j], 0.f) + 1e-6f) * my_isc;
                q3s[lt * QP + lane] = t * t * t * a_s[lt];
            }
        }
        __syncthreads();

        // Phase B: z per token (thread = token)
        {
            float zd = 0.f;
#pragma unroll
            for (int k4 = 0; k4 < 8; ++k4) {
                const float4 q = *(const float4*)&q3s[tid * QP + 4 * k4];
                const float4 kk = *(const float4*)&ks[4 * k4];
                zd += q.x * kk.x + q.y * kk.y + q.z * kk.z + q.w * kk.w;
            }
            zs[tid] = 1.f / (zd + 1e-6f);
        }
        __syncthreads();

        // Phase C: matvec + RMW into out
#pragma unroll
        for (int c = 0; c < 4; ++c) {
            float ov[8];
#pragma unroll
            for (int j = 0; j < 8; ++j) {
                const int lt = wid * 32 + c * 8 + j;
                ov[j] = out[(size_t)(b * NTOK + s0 + lt) * NC + h * HD + lane];
            }
#pragma unroll
            for (int j = 0; j < 8; ++j) {
                const int lt = wid * 32 + c * 8 + j;
                float mv0 = 0.f, mv1 = 0.f;
#pragma unroll
                for (int k4 = 0; k4 < 8; ++k4) {
                    const float4 q = *(const float4*)&q3s[lt * QP + 4 * k4];
                    mv0 += q.x * kreg[4 * k4 + 0] + q.z * kreg[4 * k4 + 2];
                    mv1 += q.y * kreg[4 * k4 + 1] + q.w * kreg[4 * k4 + 3];
                }
                out[(size_t)(b * NTOK + s0 + lt) * NC + h * HD + lane] =
                    ov[j] + zs[lt] * (mv0 + mv1);
            }
        }
        __syncthreads();
    }
}

// ---------------------------------------------------------------------------
extern "C" void kernel_launch(void* const* d_in, const int* in_sizes, int n_in,
                              void* d_out, int out_size)
{
    const float* qkv   = (const float*)d_in[0];
    const float* pos   = (const float*)d_in[1];
    const float* scale = (const float*)d_in[2];
    const float* w_v   = (const float*)d_in[3];
    const float* b_v   = (const float*)d_in[4];
    const float* w_dwc = (const float*)d_in[5];
    const float* b_dwc = (const float*)d_in[6];
    float* out = (float*)d_out;

    const int smem_conv = 20 * 20 * 32 * sizeof(float);   // 51200 B
    cudaFuncSetAttribute(k_conv, cudaFuncAttributeMaxDynamicSharedMemorySize, smem_conv);

    dim3 g1(NPART, NB);
    k_stats<<<g1, 512>>>(qkv, pos, scale);

    k_reduce<<<256, 256>>>();

    dim3 gc(16, NHEAD, NB);
    k_conv<<<gc, 256, smem_conv>>>(qkv, w_v, b_v, w_dwc, b_dwc, out);

    dim3 ga(8, NHEAD, NB);
    k_attn<<<ga, 256>>>(qkv, scale, out);
}

// round 5
// speedup vs baseline: 2.0569x; 1.0430x over previous
#include <cuda_runtime.h>
#include <math.h>

#define NB 8
#define NTOK 4096
#define NC 256
#define NHEAD 8
#define HD 32
#define RDIM 64
#define TILE 16
#define NPART 32

// Packed dual-fp32 FMA (sm_103a): d = a*b + c on both lanes, single issue slot.
__device__ __forceinline__ float2 ffma2(float2 a, float2 b, float2 c) {
    unsigned long long A, B, C, D;
    A = *(unsigned long long*)&a;
    B = *(unsigned long long*)&b;
    C = *(unsigned long long*)&c;
    asm("fma.rn.f32x2 %0, %1, %2, %3;" : "=l"(D) : "l"(A), "l"(B), "l"(C));
    return *(float2*)&D;
}

// Scratch (device globals: allocation is forbidden)
__device__ float g_part[NPART * NB * NHEAD * HD * HD];   // 8 MB partial kv
__device__ float g_parts[NPART * NB * NHEAD * HD];
__device__ float g_kv[NB * NHEAD * HD * HD];
__device__ float g_ksum[NB * NHEAD * HD];
__device__ float g_alpha[NB * NTOK];

// ---------------------------------------------------------------------------
// Kernel 1: focused k' + kv/ksum partials + alpha_q.
// 512 threads = 16 warps. Warp = token. Ownership: h = wid>>1, e-half = wid&1.
// ---------------------------------------------------------------------------
__global__ __launch_bounds__(512, 2) void k_stats(
    const float* __restrict__ qkv,
    const float* __restrict__ pos,
    const float* __restrict__ scale)
{
    __shared__ float s_isc[NC];
    __shared__ float sk[16][NC];
    __shared__ float sv[16][NC];

    const int tid  = threadIdx.x;
    const int wid  = tid >> 5;
    const int lane = tid & 31;
    const int b    = blockIdx.y;
    const int bx   = blockIdx.x;

    if (tid < NC) s_isc[tid] = 1.f / log1pf(expf(scale[tid]));
    __syncthreads();

    const float* qb = qkv + (size_t)b * NTOK * NC;
    const float* kb = qkv + ((size_t)NB + b) * NTOK * NC;
    const float* vb = qkv + ((size_t)2 * NB + b) * NTOK * NC;

    const int h    = wid >> 1;
    const int half = wid & 1;
    const int d    = lane;

    float2 acc2[8];
#pragma unroll
    for (int e = 0; e < 8; ++e) acc2[e] = make_float2(0.f, 0.f);
    float accs = 0.f;

    const float4 iscA = ((const float4*)s_isc)[lane];
    const float4 iscB = ((const float4*)s_isc)[lane + 32];

    const int i0 = bx * (NTOK / NPART);          // 128 tokens per block

    for (int it = 0; it < (NTOK / NPART) / 16; ++it) {
        const int i = i0 + it * 16 + wid;
        const size_t base = (size_t)i * NC;

        const float4* q4 = (const float4*)(qb + base);
        const float4* k4 = (const float4*)(kb + base);
        const float4* p4 = (const float4*)(pos + base);
        const float4* v4 = (const float4*)(vb + base);

        float4 qA = q4[lane],      qB = q4[lane + 32];
        float4 kA = k4[lane],      kB = k4[lane + 32];
        float4 pA = p4[lane],      pB = p4[lane + 32];
        float4 vA = v4[lane],      vB = v4[lane + 32];

        float s2q = 0.f, s6q = 0.f, s2k = 0.f, s6k = 0.f;
        float4 t3A, t3B;

#define PROC(qc, kc, pc, ic, outc)                                  \
        {                                                           \
            float tq = (fmaxf(qc, 0.f) + 1e-6f) * ic;               \
            float tk = (fmaxf(kc + pc, 0.f) + 1e-6f) * ic;          \
            s2q += tq * tq;                                         \
            float tq3 = tq * tq * tq; s6q += tq3 * tq3;             \
            s2k += tk * tk;                                         \
            float tk3 = tk * tk * tk; s6k += tk3 * tk3;             \
            outc = tk3;                                             \
        }
        PROC(qA.x, kA.x, pA.x, iscA.x, t3A.x)
        PROC(qA.y, kA.y, pA.y, iscA.y, t3A.y)
        PROC(qA.z, kA.z, pA.z, iscA.z, t3A.z)
        PROC(qA.w, kA.w, pA.w, iscA.w, t3A.w)
        PROC(qB.x, kB.x, pB.x, iscB.x, t3B.x)
        PROC(qB.y, kB.y, pB.y, iscB.y, t3B.y)
        PROC(qB.z, kB.z, pB.z, iscB.z, t3B.z)
        PROC(qB.w, kB.w, pB.w, iscB.w, t3B.w)
#undef PROC

#pragma unroll
        for (int off = 16; off; off >>= 1) {
            s2q += __shfl_xor_sync(0xffffffffu, s2q, off);
            s6q += __shfl_xor_sync(0xffffffffu, s6q, off);
            s2k += __shfl_xor_sync(0xffffffffu, s2k, off);
            s6k += __shfl_xor_sync(0xffffffffu, s6k, off);
        }
        const float ak = sqrtf(s2k / s6k);
        if (lane == 0) g_alpha[b * NTOK + i] = sqrtf(s2q / s6q);

        float4* skp = (float4*)&sk[wid][0];
        float4* svp = (float4*)&sv[wid][0];
        skp[lane]      = make_float4(t3A.x * ak, t3A.y * ak, t3A.z * ak, t3A.w * ak);
        skp[lane + 32] = make_float4(t3B.x * ak, t3B.y * ak, t3B.z * ak, t3B.w * ak);
        svp[lane]      = vA;
        svp[lane + 32] = vB;
        __syncthreads();

#pragma unroll
        for (int c = 0; c < 2; ++c) {
            float kd[8];
#pragma unroll
            for (int t8 = 0; t8 < 8; ++t8) {
                kd[t8] = sk[c * 8 + t8][h * HD + d];
                accs += kd[t8];
            }
#pragma unroll
            for (int t8 = 0; t8 < 8; ++t8) {
                const float2 kd2 = make_float2(kd[t8], kd[t8]);
                const float4* vv = (const float4*)&sv[c * 8 + t8][h * HD + half * 16];
#pragma unroll
                for (int e4 = 0; e4 < 4; ++e4) {
                    const float4 v = vv[e4];
                    acc2[e4 * 2 + 0] = ffma2(kd2, make_float2(v.x, v.y), acc2[e4 * 2 + 0]);
                    acc2[e4 * 2 + 1] = ffma2(kd2, make_float2(v.z, v.w), acc2[e4 * 2 + 1]);
                }
            }
        }
        __syncthreads();
    }

    float4* dst = (float4*)&g_part[((((size_t)bx * NB + b) * NHEAD + h) * HD + d) * HD + half * 16];
#pragma unroll
    for (int e4 = 0; e4 < 4; ++e4)
        dst[e4] = make_float4(acc2[e4 * 2].x, acc2[e4 * 2].y,
                              acc2[e4 * 2 + 1].x, acc2[e4 * 2 + 1].y);
    if (half == 0)
        g_parts[(((size_t)bx * NB + b) * NHEAD + h) * HD + d] = accs;
}

// ---------------------------------------------------------------------------
// Kernel 2: reduce NPART partials -> g_kv, g_ksum.
// ---------------------------------------------------------------------------
__global__ __launch_bounds__(256) void k_reduce()
{
    const int tid = threadIdx.x;
    const int bh  = blockIdx.x >> 2;
    const int qtr = blockIdx.x & 3;
    const int entry = qtr * 256 + tid;

    float s = 0.f;
#pragma unroll 8
    for (int p = 0; p < NPART; ++p)
        s += g_part[((size_t)p * NB * NHEAD + bh) * (HD * HD) + entry];
    g_kv[(size_t)bh * HD * HD + entry] = s;

    if (qtr == 0 && tid < HD) {
        float ss = 0.f;
#pragma unroll 8
        for (int p = 0; p < NPART; ++p)
            ss += g_parts[((size_t)p * NB * NHEAD + bh) * HD + tid];
        g_ksum[(size_t)bh * HD + tid] = ss;
    }
}

// ---------------------------------------------------------------------------
// Kernel 3: merged 5x5 depthwise conv (LePE folded in) + bias -> writes out.
// ---------------------------------------------------------------------------
__global__ __launch_bounds__(256, 3) void k_conv(
    const float* __restrict__ qkv,
    const float* __restrict__ w_v,
    const float* __restrict__ b_v,
    const float* __restrict__ w_dwc,
    const float* __restrict__ b_dwc,
    float* __restrict__ out)
{
    extern __shared__ float vt[];                 // [20][20][32]

    const int tid  = threadIdx.x;
    const int lane = tid & 31;
    const int wid  = tid >> 5;
    const int b    = blockIdx.z;
    const int h    = blockIdx.y;
    const int tile = blockIdx.x;
    const int r0 = (tile >> 2) * TILE;
    const int c0 = (tile & 3) * TILE;

    const float* vb = qkv + ((size_t)2 * NB + b) * NTOK * NC;

#pragma unroll
    for (int u = 0; u < 13; ++u) {
        const int idx = tid + u * 256;
        if (idx < 20 * 20 * 8) {
            const int e4 = idx & 7;
            const int rc = idx >> 3;
            const int col = rc % 20, row = rc / 20;
            const int gy = r0 + row - 2, gx = c0 + col - 2;
            float4 v = make_float4(0.f, 0.f, 0.f, 0.f);
            if (gy >= 0 && gy < RDIM && gx >= 0 && gx < RDIM)
                v = *(const float4*)&vb[(size_t)(gy * RDIM + gx) * NC + h * HD + e4 * 4];
            ((float4*)vt)[idx] = v;
        }
    }

    float wreg[25];
#pragma unroll
    for (int t = 0; t < 25; ++t) {
        const int ky = t / 5, kx = t % 5;
        float w = w_dwc[lane * 25 + t];
        if (ky >= 1 && ky <= 3 && kx >= 1 && kx <= 3)
            w += w_v[(h * HD + lane) * 9 + (ky - 1) * 3 + (kx - 1)];
        wreg[t] = w;
    }
    const float my_bias = b_v[h * HD + lane] + b_dwc[lane];
    __syncthreads();

#pragma unroll
    for (int ty = 0; ty < 2; ++ty) {
        const int lr = wid * 2 + ty;
        const int gy = r0 + lr;

        float ring[5][5];
#pragma unroll
        for (int s = 0; s < 4; ++s)
#pragma unroll
            for (int ky = 0; ky < 5; ++ky)
                ring[s][ky] = vt[((lr + ky) * 20 + s) * 32 + lane];

#pragma unroll
        for (int lc = 0; lc < TILE; ++lc) {
            const int slot = (lc + 4) % 5;
#pragma unroll
            for (int ky = 0; ky < 5; ++ky)
                ring[slot][ky] = vt[((lr + ky) * 20 + lc + 4) * 32 + lane];

            float accv = my_bias;
#pragma unroll
            for (int ky = 0; ky < 5; ++ky)
#pragma unroll
                for (int kx = 0; kx < 5; ++kx)
                    accv += ring[(lc + kx) % 5][ky] * wreg[ky * 5 + kx];

            const int i = gy * RDIM + (c0 + lc);
            out[(size_t)(b * NTOK + i) * NC + h * HD + lane] = accv;
        }
    }
}

// ---------------------------------------------------------------------------
// Kernel 4: attention term, out += z * (q3 @ kv). FFMA2 matvec.
// ---------------------------------------------------------------------------
#define QP 36

__global__ __launch_bounds__(256, 4) void k_attn(
    const float* __restrict__ qkv,
    const float* __restrict__ scale,
    float* __restrict__ out)
{
    __shared__ float q3s[256 * QP];
    __shared__ float a_s[256];
    __shared__ float zs[256];
    __shared__ float ks[HD];

    const int tid  = threadIdx.x;
    const int lane = tid & 31;
    const int wid  = tid >> 5;
    const int b    = blockIdx.z;
    const int h    = blockIdx.y;

    const float* qb = qkv + (size_t)b * NTOK * NC;

    // kv column for this lane, packed into 16 float2 pairs (d, d+1)
    float2 kp[16];
#pragma unroll
    for (int j = 0; j < 16; ++j) {
        const float a = g_kv[(((size_t)b * NHEAD + h) * HD + 2 * j) * HD + lane];
        const float c = g_kv[(((size_t)b * NHEAD + h) * HD + 2 * j + 1) * HD + lane];
        kp[j] = make_float2(a, c);
    }
    const float my_isc = 1.f / log1pf(expf(scale[h * HD + lane]));
    if (tid < HD) ks[tid] = g_ksum[((size_t)b * NHEAD + h) * HD + tid];

    for (int s = 0; s < 2; ++s) {
        const int s0 = blockIdx.x * 512 + s * 256;

        a_s[tid] = g_alpha[b * NTOK + s0 + tid];
        __syncthreads();

        // Phase A: focused q3 (batched LDGs)
#pragma unroll
        for (int c = 0; c < 2; ++c) {
            float qv[16];
#pragma unroll
            for (int j = 0; j < 16; ++j) {
                const int lt = wid * 32 + c * 16 + j;
                qv[j] = qb[(size_t)(s0 + lt) * NC + h * HD + lane];
            }
#pragma unroll
            for (int j = 0; j < 16; ++j) {
                const int lt = wid * 32 + c * 16 + j;
                const float t = (fmaxf(qv[j], 0.f) + 1e-6f) * my_isc;
                q3s[lt * QP + lane] = t * t * t * a_s[lt];
            }
        }
        __syncthreads();

        // Phase B: z per token (thread = token), FFMA2 dot
        {
            float2 zd = make_float2(0.f, 0.f);
#pragma unroll
            for (int k4 = 0; k4 < 8; ++k4) {
                const float4 q = *(const float4*)&q3s[tid * QP + 4 * k4];
                const float4 kk = *(const float4*)&ks[4 * k4];
                zd = ffma2(make_float2(q.x, q.y), make_float2(kk.x, kk.y), zd);
                zd = ffma2(make_float2(q.z, q.w), make_float2(kk.z, kk.w), zd);
            }
            zs[tid] = 1.f / (zd.x + zd.y + 1e-6f);
        }
        __syncthreads();

        // Phase C: FFMA2 matvec + RMW into out
#pragma unroll
        for (int c = 0; c < 4; ++c) {
            float ov[8];
#pragma unroll
            for (int j = 0; j < 8; ++j) {
                const int lt = wid * 32 + c * 8 + j;
                ov[j] = out[(size_t)(b * NTOK + s0 + lt) * NC + h * HD + lane];
            }
#pragma unroll
            for (int j = 0; j < 8; ++j) {
                const int lt = wid * 32 + c * 8 + j;
                float2 m0 = make_float2(0.f, 0.f);
                float2 m1 = make_float2(0.f, 0.f);
#pragma unroll
                for (int k4 = 0; k4 < 8; ++k4) {
                    const float4 q = *(const float4*)&q3s[lt * QP + 4 * k4];
                    m0 = ffma2(make_float2(q.x, q.y), kp[2 * k4 + 0], m0);
                    m1 = ffma2(make_float2(q.z, q.w), kp[2 * k4 + 1], m1);
                }
                out[(size_t)(b * NTOK + s0 + lt) * NC + h * HD + lane] =
                    ov[j] + zs[lt] * (m0.x + m0.y + m1.x + m1.y);
            }
        }
        __syncthreads();
    }
}

// ---------------------------------------------------------------------------
extern "C" void kernel_launch(void* const* d_in, const int* in_sizes, int n_in,
                              void* d_out, int out_size)
{
    const float* qkv   = (const float*)d_in[0];
    const float* pos   = (const float*)d_in[1];
    const float* scale = (const float*)d_in[2];
    const float* w_v   = (const float*)d_in[3];
    const float* b_v   = (const float*)d_in[4];
    const float* w_dwc = (const float*)d_in[5];
    const float* b_dwc = (const float*)d_in[6];
    float* out = (float*)d_out;

    const int smem_conv = 20 * 20 * 32 * sizeof(float);
    cudaFuncSetAttribute(k_conv, cudaFuncAttributeMaxDynamicSharedMemorySize, smem_conv);

    dim3 g1(NPART, NB);
    k_stats<<<g1, 512>>>(qkv, pos, scale);

    k_reduce<<<256, 256>>>();

    dim3 gc(16, NHEAD, NB);
    k_conv<<<gc, 256, smem_conv>>>(qkv, w_v, b_v, w_dwc, b_dwc, out);

    dim3 ga(8, NHEAD, NB);
    k_attn<<<ga, 256>>>(qkv, scale, out);
}